// round 15
// baseline (speedup 1.0000x reference)
#include <cuda_runtime.h>
#include <cuda_fp16.h>
#include <math.h>
#include <stdint.h>

#define SLOPE 0.2f
#define AROW 272u

// Shapes fixed: B=8, N=2048, D=128.
__device__ float g_h[8 * 2048 * 128];     // h = x @ W (fp32)
__device__ __half g_hT[8 * 128 * 2048];   // fp16 h, transposed [b][o][j]
__device__ __half g_WT[128 * 128];        // fp16 W^T [o][k]
__device__ float g_ssrc[8 * 2048];
__device__ float g_sdst[8 * 2048];
__device__ float g_v[8 * 2048];
__device__ int   g_perm[8 * 2048];
__device__ float g_w1[8 * 2048];
__device__ float g_w02[8 * 2048];
__device__ float g_suf1[8 * 2049 * 128];
__device__ float g_pre02[8 * 2049 * 128];
__device__ float g_sufD1[8 * 2049];
__device__ float g_preD02[8 * 2049];
__device__ float g_cs1[8 * 32 * 128];     // chunk sums (k4 phase A)
__device__ float g_cs02[8 * 32 * 128];

// ---------------------------------------------------------------------------
// helpers
// ---------------------------------------------------------------------------
__device__ __forceinline__ uint32_t smem_u32(const void* p) {
    uint32_t a;
    asm("{ .reg .u64 t; cvta.to.shared.u64 t, %1; cvt.u32.u64 %0, t; }" : "=r"(a) : "l"(p));
    return a;
}
__device__ __forceinline__ void ldmx4(uint32_t* r, uint32_t addr) {
    asm volatile("ldmatrix.sync.aligned.m8n8.x4.shared.b16 {%0,%1,%2,%3}, [%4];"
                 : "=r"(r[0]), "=r"(r[1]), "=r"(r[2]), "=r"(r[3]) : "r"(addr));
}
__device__ __forceinline__ void mma16816(float* d, const uint32_t* a, const uint32_t* b) {
    asm volatile(
        "mma.sync.aligned.m16n8k16.row.col.f32.f16.f16.f32 "
        "{%0,%1,%2,%3}, {%4,%5,%6,%7}, {%8,%9}, {%0,%1,%2,%3};"
        : "+f"(d[0]), "+f"(d[1]), "+f"(d[2]), "+f"(d[3])
        : "r"(a[0]), "r"(a[1]), "r"(a[2]), "r"(a[3]), "r"(b[0]), "r"(b[1]));
}
__device__ __forceinline__ uint32_t cvt2h(float hi, float lo) {
    uint32_t r;
    asm("cvt.rn.f16x2.f32 %0, %1, %2;" : "=r"(r) : "f"(hi), "f"(lo));
    return r;
}
__device__ __forceinline__ void sts128(uint32_t a, uint32_t x, uint32_t y, uint32_t z, uint32_t w) {
    asm volatile("st.shared.v4.b32 [%0], {%1,%2,%3,%4};" :: "r"(a), "r"(x), "r"(y), "r"(z), "r"(w) : "memory");
}

// ---------------------------------------------------------------------------
// K0: W [k][o] fp32 -> g_WT [o][k] fp16
// ---------------------------------------------------------------------------
__global__ __launch_bounds__(256) void k0_wt(const float* __restrict__ W) {
    __shared__ float t[32][33];
    const int k0 = blockIdx.x * 32, o0 = blockIdx.y * 32;
    const int tx = threadIdx.x, ty = threadIdx.y;
#pragma unroll
    for (int r = 0; r < 32; r += 8)
        t[ty + r][tx] = W[(size_t)(k0 + ty + r) * 128 + o0 + tx];
    __syncthreads();
#pragma unroll
    for (int r = 0; r < 32; r += 8)
        g_WT[(size_t)(o0 + ty + r) * 128 + k0 + tx] = __float2half_rn(t[tx][ty + r]);
}

// ---------------------------------------------------------------------------
// K1: h = x @ W via fp16 mma.sync + FUSED s_src/s_dst computation
// ---------------------------------------------------------------------------
#define K1_TILE (128u * AROW)
#define K1_SMEM (2u * K1_TILE)

__global__ __launch_bounds__(256) void k1_mma(const float* __restrict__ x,
                                              const float* __restrict__ a) {
    extern __shared__ __align__(128) char dsm[];
    __shared__ float aS[256];
    __shared__ float sPS[4][128], sPD[4][128];
    const uint32_t sb = smem_u32(dsm);
    const uint32_t OFF_X = 0u, OFF_W = K1_TILE;
    const int tid = threadIdx.x;
    const size_t i0 = (size_t)blockIdx.x * 128;

    aS[tid] = a[tid];

#pragma unroll
    for (int p = 0; p < 8; p++) {
        int idx = p * 256 + tid;
        int brow = idx >> 4, seg = idx & 15;
        uint4 v = *(const uint4*)(g_WT + (size_t)brow * 128 + seg * 8);
        sts128(sb + OFF_W + (uint32_t)brow * AROW + (uint32_t)seg * 16, v.x, v.y, v.z, v.w);
    }
    {
        const int row = tid >> 1, half = tid & 1;
        const float* xr = x + (i0 + row) * 128 + half * 64;
        const uint32_t sBase = sb + OFF_X + (uint32_t)row * AROW + (uint32_t)half * 128;
#pragma unroll
        for (int p = 0; p < 8; p++) {
            float4 u = *(const float4*)(xr + p * 8);
            float4 w = *(const float4*)(xr + p * 8 + 4);
            sts128(sBase + p * 16, cvt2h(u.y, u.x), cvt2h(u.w, u.z),
                   cvt2h(w.y, w.x), cvt2h(w.w, w.z));
        }
    }
    __syncthreads();

    const int warp = tid >> 5, lane = tid & 31;
    const int wi = warp & 1, wo = warp >> 1;
    const int obase = wo * 32;
    const uint32_t aLane = (uint32_t)(wi * 64 + (lane & 15)) * AROW + ((lane >> 4) << 4);
    const uint32_t bLane = (uint32_t)(obase + (lane & 7) + ((lane & 16) >> 1)) * AROW + ((lane & 8) << 1);

    float acc[4][4][4];
#pragma unroll
    for (int mf = 0; mf < 4; mf++)
#pragma unroll
        for (int nf = 0; nf < 4; nf++)
#pragma unroll
            for (int e = 0; e < 4; e++) acc[mf][nf][e] = 0.f;

#pragma unroll
    for (int kk = 0; kk < 8; kk++) {
        uint32_t aF[4][4], bF[8];
        const uint32_t aAddr = sb + OFF_X + aLane + kk * 32;
        const uint32_t bAddr = sb + OFF_W + bLane + kk * 32;
#pragma unroll
        for (int mf = 0; mf < 4; mf++) ldmx4(aF[mf], aAddr + (uint32_t)mf * (16u * AROW));
        ldmx4(&bF[0], bAddr);
        ldmx4(&bF[4], bAddr + 16u * AROW);
#pragma unroll
        for (int mf = 0; mf < 4; mf++)
#pragma unroll
            for (int nf = 0; nf < 4; nf++)
                mma16816(acc[mf][nf], aF[mf], &bF[nf * 2]);
    }

#pragma unroll
    for (int mf = 0; mf < 4; mf++) {
#pragma unroll
        for (int hh = 0; hh < 2; hh++) {
            const int rl = wi * 64 + mf * 16 + hh * 8 + (lane >> 2);
            float* dst = &g_h[(i0 + rl) * 128];
            float p1 = 0.f, p2 = 0.f;
#pragma unroll
            for (int nf = 0; nf < 4; nf++) {
                const int o = obase + nf * 8 + (lane & 3) * 2;
                float v0 = acc[mf][nf][hh * 2 + 0];
                float v1 = acc[mf][nf][hh * 2 + 1];
                float2 r; r.x = v0; r.y = v1;
                *(float2*)&dst[o] = r;
                p1 += v0 * aS[o] + v1 * aS[o + 1];
                p2 += v0 * aS[128 + o] + v1 * aS[128 + o + 1];
            }
            p1 += __shfl_xor_sync(0xffffffffu, p1, 1);
            p1 += __shfl_xor_sync(0xffffffffu, p1, 2);
            p2 += __shfl_xor_sync(0xffffffffu, p2, 1);
            p2 += __shfl_xor_sync(0xffffffffu, p2, 2);
            if ((lane & 3) == 0) { sPS[wo][rl] = p1; sPD[wo][rl] = p2; }
        }
    }
    __syncthreads();
    if (tid < 128) {
        float s1 = sPS[0][tid] + sPS[1][tid] + sPS[2][tid] + sPS[3][tid];
        float s2 = sPD[0][tid] + sPD[1][tid] + sPD[2][tid] + sPD[3][tid];
        g_ssrc[i0 + tid] = s1;
        g_sdst[i0 + tid] = s2;
    }
}

// ---------------------------------------------------------------------------
// K1b: transpose h -> [b][o][j], convert to fp16  (R13 proven version)
// ---------------------------------------------------------------------------
__global__ __launch_bounds__(256) void k1b_split() {
    __shared__ float t[32][33];
    const int b = blockIdx.z;
    const int j0 = blockIdx.x * 32, o0 = blockIdx.y * 32;
    const int tx = threadIdx.x, ty = threadIdx.y;
#pragma unroll
    for (int r = 0; r < 32; r += 8)
        t[ty + r][tx] = g_h[((size_t)b * 2048 + j0 + ty + r) * 128 + o0 + tx];
    __syncthreads();
#pragma unroll
    for (int r = 0; r < 32; r += 8) {
        float v = t[tx][ty + r];
        size_t idx = ((size_t)b * 128 + o0 + ty + r) * 2048 + j0 + tx;
        g_hT[idx] = __float2half_rn(v);
    }
}

// ---------------------------------------------------------------------------
// K3: rank sort — 512 thr (R13 proven version)
// ---------------------------------------------------------------------------
__global__ __launch_bounds__(512) void k3_sort() {
    __shared__ float s[2048];
    __shared__ int part[16][128];
    const int b = blockIdx.y;
    const int tid = threadIdx.x;
    for (int idx = tid; idx < 2048; idx += 512) s[idx] = g_sdst[b * 2048 + idx];
    __syncthreads();
    const int g = tid & 31;
    const int ck = tid >> 5;
    const int jl0 = g * 4;
    const int jg0 = blockIdx.x * 128 + jl0;
    const float4 my = *(const float4*)&s[jg0];
    int r0 = 0, r1 = 0, r2 = 0, r3 = 0;
    const int q0 = ck * 128;
#pragma unroll 8
    for (int q = q0; q < q0 + 128; q += 4) {
        const float4 v = *(const float4*)&s[q];
        r0 += (v.x < my.x) || (v.x == my.x && (q + 0) < (jg0 + 0));
        r1 += (v.x < my.y) || (v.x == my.y && (q + 0) < (jg0 + 1));
        r2 += (v.x < my.z) || (v.x == my.z && (q + 0) < (jg0 + 2));
        r3 += (v.x < my.w) || (v.x == my.w && (q + 0) < (jg0 + 3));
        r0 += (v.y < my.x) || (v.y == my.x && (q + 1) < (jg0 + 0));
        r1 += (v.y < my.y) || (v.y == my.y && (q + 1) < (jg0 + 1));
        r2 += (v.y < my.z) || (v.y == my.z && (q + 1) < (jg0 + 2));
        r3 += (v.y < my.w) || (v.y == my.w && (q + 1) < (jg0 + 3));
        r0 += (v.z < my.x) || (v.z == my.x && (q + 2) < (jg0 + 0));
        r1 += (v.z < my.y) || (v.z == my.y && (q + 2) < (jg0 + 1));
        r2 += (v.z < my.z) || (v.z == my.z && (q + 2) < (jg0 + 2));
        r3 += (v.z < my.w) || (v.z == my.w && (q + 2) < (jg0 + 3));
        r0 += (v.w < my.x) || (v.w == my.x && (q + 3) < (jg0 + 0));
        r1 += (v.w < my.y) || (v.w == my.y && (q + 3) < (jg0 + 1));
        r2 += (v.w < my.z) || (v.w == my.z && (q + 3) < (jg0 + 2));
        r3 += (v.w < my.w) || (v.w == my.w && (q + 3) < (jg0 + 3));
    }
    part[ck][jl0 + 0] = r0; part[ck][jl0 + 1] = r1;
    part[ck][jl0 + 2] = r2; part[ck][jl0 + 3] = r3;
    __syncthreads();
    if (tid < 128) {
        int r = 0;
#pragma unroll
        for (int c = 0; c < 16; c++) r += part[c][tid];
        const float mv = s[blockIdx.x * 128 + tid];
        const int base = b * 2048;
        g_v[base + r]    = mv;
        g_perm[base + r] = blockIdx.x * 128 + tid;
        g_w1[base + r]   = expf(mv);
        g_w02[base + r]  = expf(SLOPE * mv);
    }
}

// ---------------------------------------------------------------------------
// K4a: chunk sums — grid (4, 8, 32), 256 thr
// ---------------------------------------------------------------------------
__global__ __launch_bounds__(256) void k4a_sums() {
    __shared__ float s1[8][33], s02[8][33];
    const int ol = threadIdx.x & 31, rs = threadIdx.x >> 5;
    const int o = blockIdx.x * 32 + ol;
    const int b = blockIdx.y, c = blockIdx.z;
    const int base = b * 2048;
    const int r0 = c * 64 + rs * 8;
    float a1 = 0.f, a02 = 0.f;
#pragma unroll
    for (int r = r0; r < r0 + 8; r++) {
        int j = g_perm[base + r];
        float hv = g_h[((size_t)(base + j)) * 128 + o];
        a1  += g_w1[base + r]  * hv;
        a02 += g_w02[base + r] * hv;
    }
    s1[rs][ol] = a1; s02[rs][ol] = a02;
    __syncthreads();
    if (rs == 0) {
        float t1 = 0.f, t02 = 0.f;
#pragma unroll
        for (int q = 0; q < 8; q++) { t1 += s1[q][ol]; t02 += s02[q][ol]; }
        g_cs1[(b * 32 + c) * 128 + o]  = t1;
        g_cs02[(b * 32 + c) * 128 + o] = t02;
    }
}

// ---------------------------------------------------------------------------
// K4b: scan + table write — grid (4, 8, 32), 256 thr
// ---------------------------------------------------------------------------
__global__ __launch_bounds__(256) void k4b_scan() {
    __shared__ float s1[8][33], s02[8][33];
    const int ol = threadIdx.x & 31, rs = threadIdx.x >> 5;
    const int o = blockIdx.x * 32 + ol;
    const int b = blockIdx.y, c = blockIdx.z;
    const int base = b * 2048;

    float off1 = 0.f, off02 = 0.f, tot1 = 0.f;
#pragma unroll
    for (int q = 0; q < 32; q++) {
        float v1  = g_cs1[(b * 32 + q) * 128 + o];
        float v02 = g_cs02[(b * 32 + q) * 128 + o];
        tot1 += v1;
        if (q < c) { off1 += v1; off02 += v02; }
    }
    const int r0 = c * 64 + rs * 8;
    float a1 = 0.f, a02 = 0.f;
#pragma unroll
    for (int r = r0; r < r0 + 8; r++) {
        int j = g_perm[base + r];
        float hv = g_h[((size_t)(base + j)) * 128 + o];
        a1  += g_w1[base + r]  * hv;
        a02 += g_w02[base + r] * hv;
    }
    s1[rs][ol] = a1; s02[rs][ol] = a02;
    __syncthreads();
    float run1 = off1, run02 = off02;
    for (int q = 0; q < rs; q++) { run1 += s1[q][ol]; run02 += s02[q][ol]; }
    const size_t tbase = ((size_t)b * 2049) * 128 + o;
#pragma unroll
    for (int r = r0; r < r0 + 8; r++) {
        int j = g_perm[base + r];
        float hv = g_h[((size_t)(base + j)) * 128 + o];
        g_suf1[tbase + (size_t)r * 128]  = tot1 - run1;
        run1 += g_w1[base + r] * hv;
        g_pre02[tbase + (size_t)r * 128] = run02;
        run02 += g_w02[base + r] * hv;
    }
    if (c == 31 && rs == 7) {
        g_suf1[tbase + (size_t)2048 * 128]  = 0.f;
        g_pre02[tbase + (size_t)2048 * 128] = run02;
    }
}

// K4d: denominators (tiny, fp64)
__global__ __launch_bounds__(32) void k4d_scanD() {
    __shared__ double cs1[16], cs02[16], off1[16], off02[16], tot[2];
    const int b = blockIdx.x;
    const int c = threadIdx.x;
    const int base = b * 2048;
    if (c < 16) {
        double a1 = 0.0, a02 = 0.0;
        for (int r = c * 128; r < c * 128 + 128; r++) {
            a1 += (double)g_w1[base + r]; a02 += (double)g_w02[base + r];
        }
        cs1[c] = a1; cs02[c] = a02;
    }
    __syncthreads();
    if (c == 0) {
        double r1 = 0.0, r2 = 0.0;
        for (int q = 0; q < 16; q++) {
            off1[q] = r1; r1 += cs1[q];
            off02[q] = r2; r2 += cs02[q];
        }
        tot[0] = r1; tot[1] = r2;
    }
    __syncthreads();
    if (c < 16) {
        double run1 = off1[c], run02 = off02[c], t1 = tot[0];
        const size_t tb = (size_t)b * 2049;
        for (int r = c * 128; r < c * 128 + 128; r++) {
            g_sufD1[tb + r] = (float)(t1 - run1);
            run1 += (double)g_w1[base + r];
            g_preD02[tb + r] = (float)run02;
            run02 += (double)g_w02[base + r];
        }
        if (c == 15) { g_sufD1[tb + 2048] = 0.f; g_preD02[tb + 2048] = (float)run02; }
    }
}

// ---------------------------------------------------------------------------
// K5: fp16 mma.sync GEMM (adj@h) + attention epilogue + lrelu
// NEW: CTA tile 64(i) x 128(o), grid (32, 8) = 256 CTAs, 256 thr = 8 warps
// (2 wi x 4 wo, warp 32x32). SMEM/stage = 51KB, 2 stages = 102KB ->
// __launch_bounds__(256, 2): TWO CTAs per SM interleave barriers/latency.
// ---------------------------------------------------------------------------
#define A_TILE (64u * AROW)              // 17408
#define B_TILE (128u * AROW)             // 34816
#define OFF_A 0u
#define OFF_B A_TILE
#define STG_BYTES (A_TILE + B_TILE)      // 52224
#define K5_SMEM (2u * STG_BYTES)         // 104448

__global__ __launch_bounds__(256, 2) void k5_main(const float* __restrict__ adj,
                                                  float* __restrict__ out) {
    extern __shared__ __align__(128) char dsm[];
    __shared__ int kS[64];
    __shared__ float e1S[64], e02S[64], dinvS[64];
    const uint32_t sb = smem_u32(dsm);
    const int tid = threadIdx.x;
    const int b = blockIdx.y;
    const int i0 = blockIdx.x * 64;

    // --- binary-search setup ---
    {
        float* vS = (float*)dsm;
        for (int idx = tid; idx < 2048; idx += 256) vS[idx] = g_v[b * 2048 + idx];
        __syncthreads();
        if (tid < 64) {
            float si = g_ssrc[b * 2048 + i0 + tid];
            float target = -si;
            int lo = 0, hi = 2048;
            while (lo < hi) { int mid = (lo + hi) >> 1; if (vS[mid] < target) lo = mid + 1; else hi = mid; }
            float e1 = expf(si), e02 = expf(SLOPE * si);
            float Dv = e1 * g_sufD1[(size_t)b * 2049 + lo] + e02 * g_preD02[(size_t)b * 2049 + lo];
            kS[tid] = lo; e1S[tid] = e1; e02S[tid] = e02; dinvS[tid] = 1.0f / Dv;
        }
        __syncthreads();
    }

    const int warp = tid >> 5, lane = tid & 31;

    // A loader: 4 passes; row = p*16 + warp*2 + (lane>>4); 32B fp32 per thread
    const float* adjT = adj + ((size_t)(b * 2048 + i0)) * 2048;
    const int aRowOff = warp * 2 + (lane >> 4);           // 0..15
    const int aCol = (lane & 15) * 8;                     // float index
    const uint32_t aSts = (uint32_t)aRowOff * AROW + (uint32_t)aCol * 2;  // + p*16*AROW
    // B loader: 8 passes; idx = p*256 + tid: brow = idx>>4 (0..127), seg = idx&15
    const __half* hTb = g_hT + ((size_t)b * 128) * 2048;
    const int bRow = tid >> 4, bSeg = tid & 15;           // row + p*16
    const uint32_t bSts = (uint32_t)bRow * AROW + (uint32_t)bSeg * 16;    // + p*16*AROW

    // compute mapping: warp -> (wi 0..1, wo 0..3); warp tile 32(i) x 32(o)
    const int wi = warp & 1, wo = warp >> 1;
    const int obase = wo * 32;
    const uint32_t aLane = (uint32_t)(wi * 32 + (lane & 15)) * AROW + ((lane >> 4) << 4);
    const uint32_t bLane = (uint32_t)(obase + (lane & 7) + ((lane & 16) >> 1)) * AROW + ((lane & 8) << 1);

    float acc[2][4][4];
#pragma unroll
    for (int mf = 0; mf < 2; mf++)
#pragma unroll
        for (int nf = 0; nf < 4; nf++)
#pragma unroll
            for (int e = 0; e < 4; e++) acc[mf][nf][e] = 0.f;

    // ---- prologue: chunk 0 -> stage 0 ----
    {
#pragma unroll
        for (int p = 0; p < 4; p++) {
            const float* src = adjT + (size_t)(p * 16 + aRowOff) * 2048 + aCol;
            float4 u = *(const float4*)src;
            float4 w = *(const float4*)(src + 4);
            sts128(sb + OFF_A + aSts + (uint32_t)p * (16u * AROW),
                   cvt2h(u.y, u.x), cvt2h(u.w, u.z), cvt2h(w.y, w.x), cvt2h(w.w, w.z));
        }
#pragma unroll
        for (int p = 0; p < 8; p++) {
            uint4 v = *(const uint4*)(hTb + (size_t)(p * 16 + bRow) * 2048 + bSeg * 8);
            sts128(sb + OFF_B + bSts + (uint32_t)p * (16u * AROW), v.x, v.y, v.z, v.w);
        }
        __syncthreads();
    }

    for (int c = 0; c < 16; c++) {
        const uint32_t sCur = sb + (c & 1 ? STG_BYTES : 0u);
        const uint32_t sNxt = sb + (c & 1 ? 0u : STG_BYTES);
        const int j1 = (c + 1) * 128;
        float4 fA[8];
        uint4 fB[8];
        if (c < 15) {
#pragma unroll
            for (int p = 0; p < 4; p++) {
                const float* src = adjT + (size_t)(p * 16 + aRowOff) * 2048 + j1 + aCol;
                fA[p * 2]     = *(const float4*)src;
                fA[p * 2 + 1] = *(const float4*)(src + 4);
            }
#pragma unroll
            for (int p = 0; p < 8; p++)
                fB[p] = *(const uint4*)(hTb + (size_t)(p * 16 + bRow) * 2048 + j1 + bSeg * 8);
        }
        // ---- compute current chunk: 8 k16 steps ----
#pragma unroll
        for (int kk = 0; kk < 8; kk++) {
            uint32_t aF[2][4], bF[8];
            const uint32_t aAddr = sCur + OFF_A + aLane + kk * 32;
            const uint32_t bAddr = sCur + OFF_B + bLane + kk * 32;
            ldmx4(aF[0], aAddr);
            ldmx4(aF[1], aAddr + 16u * AROW);
            ldmx4(&bF[0], bAddr);
            ldmx4(&bF[4], bAddr + 16u * AROW);
#pragma unroll
            for (int mf = 0; mf < 2; mf++)
#pragma unroll
                for (int nf = 0; nf < 4; nf++)
                    mma16816(acc[mf][nf], aF[mf], &bF[nf * 2]);
        }
        if (c < 15) {
#pragma unroll
            for (int p = 0; p < 4; p++) {
                float4 u = fA[p * 2], w = fA[p * 2 + 1];
                sts128(sNxt + OFF_A + aSts + (uint32_t)p * (16u * AROW),
                       cvt2h(u.y, u.x), cvt2h(u.w, u.z), cvt2h(w.y, w.x), cvt2h(w.w, w.z));
            }
#pragma unroll
            for (int p = 0; p < 8; p++)
                sts128(sNxt + OFF_B + bSts + (uint32_t)p * (16u * AROW),
                       fB[p].x, fB[p].y, fB[p].z, fB[p].w);
        }
        __syncthreads();
    }

    // ---- epilogue: attention lookup + lrelu + store ----
    // warp tile rows: wi*32 + mf*16 + hh*8 + (lane>>2), 0..63
#pragma unroll
    for (int mf = 0; mf < 2; mf++) {
        const int rl0 = wi * 32 + mf * 16 + (lane >> 2);
#pragma unroll
        for (int hh = 0; hh < 2; hh++) {
            const int rl = rl0 + hh * 8;
            const int k = kS[rl];
            const float e1 = e1S[rl], e02 = e02S[rl], dinv = dinvS[rl];
            const float* suf = &g_suf1[((size_t)(b * 2049 + k)) * 128];
            const float* pre = &g_pre02[((size_t)(b * 2049 + k)) * 128];
            float* dst = &out[((size_t)(b * 2048 + i0 + rl)) * 128];
#pragma unroll
            for (int nf = 0; nf < 4; nf++) {
                const int o = obase + nf * 8 + (lane & 3) * 2;
                float2 sf = *(const float2*)&suf[o];
                float2 pf = *(const float2*)&pre[o];
                float v0 = acc[mf][nf][hh * 2 + 0] + (e1 * sf.x + e02 * pf.x) * dinv;
                float v1 = acc[mf][nf][hh * 2 + 1] + (e1 * sf.y + e02 * pf.y) * dinv;
                float2 r;
                r.x = v0 >= 0.f ? v0 : SLOPE * v0;
                r.y = v1 >= 0.f ? v1 : SLOPE * v1;
                *(float2*)&dst[o] = r;
            }
        }
    }
}

// ---------------------------------------------------------------------------
extern "C" void kernel_launch(void* const* d_in, const int* in_sizes, int n_in,
                              void* d_out, int out_size) {
    (void)in_sizes; (void)n_in; (void)out_size;
    const float* x   = (const float*)d_in[0];
    const float* adj = (const float*)d_in[1];
    const float* W   = (const float*)d_in[2];
    const float* a   = (const float*)d_in[3];
    float* out = (float*)d_out;

    cudaFuncSetAttribute(k1_mma, cudaFuncAttributeMaxDynamicSharedMemorySize, K1_SMEM);
    cudaFuncSetAttribute(k5_main, cudaFuncAttributeMaxDynamicSharedMemorySize, K5_SMEM);

    k0_wt<<<dim3(4, 4), dim3(32, 8)>>>(W);
    k1_mma<<<128, 256, K1_SMEM>>>(x, a);
    k1b_split<<<dim3(64, 4, 8), dim3(32, 8)>>>();
    k3_sort<<<dim3(16, 8), 512>>>();
    k4a_sums<<<dim3(4, 8, 32), 256>>>();
    k4b_scan<<<dim3(4, 8, 32), 256>>>();
    k4d_scanD<<<8, 32>>>();
    k5_main<<<dim3(32, 8), 256, K5_SMEM>>>(adj, out);
}

// round 16
// speedup vs baseline: 1.3456x; 1.3456x over previous
#include <cuda_runtime.h>
#include <cuda_fp16.h>
#include <math.h>
#include <stdint.h>

#define SLOPE 0.2f
#define AROW 272u

// Shapes fixed: B=8, N=2048, D=128.
__device__ float g_h[8 * 2048 * 128];     // h = x @ W (fp32)
__device__ __half g_hT[8 * 128 * 2048];   // fp16 h, transposed [b][o][j]
__device__ __half g_WT[128 * 128];        // fp16 W^T [o][k]
__device__ float g_ssrc[8 * 2048];
__device__ float g_sdst[8 * 2048];
__device__ float g_v[8 * 2048];
__device__ int   g_perm[8 * 2048];
__device__ float g_w1[8 * 2048];
__device__ float g_w02[8 * 2048];
__device__ float g_suf1[8 * 2049 * 128];
__device__ float g_pre02[8 * 2049 * 128];
__device__ float g_sufD1[8 * 2049];
__device__ float g_preD02[8 * 2049];
__device__ float g_cs1[8 * 32 * 128];     // chunk sums (k4 phase A)
__device__ float g_cs02[8 * 32 * 128];

// ---------------------------------------------------------------------------
// helpers
// ---------------------------------------------------------------------------
__device__ __forceinline__ uint32_t smem_u32(const void* p) {
    uint32_t a;
    asm("{ .reg .u64 t; cvta.to.shared.u64 t, %1; cvt.u32.u64 %0, t; }" : "=r"(a) : "l"(p));
    return a;
}
__device__ __forceinline__ void ldmx4(uint32_t* r, uint32_t addr) {
    asm volatile("ldmatrix.sync.aligned.m8n8.x4.shared.b16 {%0,%1,%2,%3}, [%4];"
                 : "=r"(r[0]), "=r"(r[1]), "=r"(r[2]), "=r"(r[3]) : "r"(addr));
}
__device__ __forceinline__ void mma16816(float* d, const uint32_t* a, const uint32_t* b) {
    asm volatile(
        "mma.sync.aligned.m16n8k16.row.col.f32.f16.f16.f32 "
        "{%0,%1,%2,%3}, {%4,%5,%6,%7}, {%8,%9}, {%0,%1,%2,%3};"
        : "+f"(d[0]), "+f"(d[1]), "+f"(d[2]), "+f"(d[3])
        : "r"(a[0]), "r"(a[1]), "r"(a[2]), "r"(a[3]), "r"(b[0]), "r"(b[1]));
}
__device__ __forceinline__ uint32_t cvt2h(float hi, float lo) {
    uint32_t r;
    asm("cvt.rn.f16x2.f32 %0, %1, %2;" : "=r"(r) : "f"(hi), "f"(lo));
    return r;
}
__device__ __forceinline__ void sts128(uint32_t a, uint32_t x, uint32_t y, uint32_t z, uint32_t w) {
    asm volatile("st.shared.v4.b32 [%0], {%1,%2,%3,%4};" :: "r"(a), "r"(x), "r"(y), "r"(z), "r"(w) : "memory");
}

// ---------------------------------------------------------------------------
// K0: W [k][o] fp32 -> g_WT [o][k] fp16
// ---------------------------------------------------------------------------
__global__ __launch_bounds__(256) void k0_wt(const float* __restrict__ W) {
    __shared__ float t[32][33];
    const int k0 = blockIdx.x * 32, o0 = blockIdx.y * 32;
    const int tx = threadIdx.x, ty = threadIdx.y;
#pragma unroll
    for (int r = 0; r < 32; r += 8)
        t[ty + r][tx] = W[(size_t)(k0 + ty + r) * 128 + o0 + tx];
    __syncthreads();
#pragma unroll
    for (int r = 0; r < 32; r += 8)
        g_WT[(size_t)(o0 + ty + r) * 128 + k0 + tx] = __float2half_rn(t[tx][ty + r]);
}

// ---------------------------------------------------------------------------
// K1: h = x @ W via fp16 mma.sync + FUSED s_src/s_dst computation
// ---------------------------------------------------------------------------
#define K1_TILE (128u * AROW)
#define K1_SMEM (2u * K1_TILE)

__global__ __launch_bounds__(256) void k1_mma(const float* __restrict__ x,
                                              const float* __restrict__ a) {
    extern __shared__ __align__(128) char dsm[];
    __shared__ float aS[256];
    __shared__ float sPS[4][128], sPD[4][128];
    const uint32_t sb = smem_u32(dsm);
    const uint32_t OFF_X = 0u, OFF_W = K1_TILE;
    const int tid = threadIdx.x;
    const size_t i0 = (size_t)blockIdx.x * 128;

    aS[tid] = a[tid];

#pragma unroll
    for (int p = 0; p < 8; p++) {
        int idx = p * 256 + tid;
        int brow = idx >> 4, seg = idx & 15;
        uint4 v = *(const uint4*)(g_WT + (size_t)brow * 128 + seg * 8);
        sts128(sb + OFF_W + (uint32_t)brow * AROW + (uint32_t)seg * 16, v.x, v.y, v.z, v.w);
    }
    {
        const int row = tid >> 1, half = tid & 1;
        const float* xr = x + (i0 + row) * 128 + half * 64;
        const uint32_t sBase = sb + OFF_X + (uint32_t)row * AROW + (uint32_t)half * 128;
#pragma unroll
        for (int p = 0; p < 8; p++) {
            float4 u = *(const float4*)(xr + p * 8);
            float4 w = *(const float4*)(xr + p * 8 + 4);
            sts128(sBase + p * 16, cvt2h(u.y, u.x), cvt2h(u.w, u.z),
                   cvt2h(w.y, w.x), cvt2h(w.w, w.z));
        }
    }
    __syncthreads();

    const int warp = tid >> 5, lane = tid & 31;
    const int wi = warp & 1, wo = warp >> 1;
    const int obase = wo * 32;
    const uint32_t aLane = (uint32_t)(wi * 64 + (lane & 15)) * AROW + ((lane >> 4) << 4);
    const uint32_t bLane = (uint32_t)(obase + (lane & 7) + ((lane & 16) >> 1)) * AROW + ((lane & 8) << 1);

    float acc[4][4][4];
#pragma unroll
    for (int mf = 0; mf < 4; mf++)
#pragma unroll
        for (int nf = 0; nf < 4; nf++)
#pragma unroll
            for (int e = 0; e < 4; e++) acc[mf][nf][e] = 0.f;

#pragma unroll
    for (int kk = 0; kk < 8; kk++) {
        uint32_t aF[4][4], bF[8];
        const uint32_t aAddr = sb + OFF_X + aLane + kk * 32;
        const uint32_t bAddr = sb + OFF_W + bLane + kk * 32;
#pragma unroll
        for (int mf = 0; mf < 4; mf++) ldmx4(aF[mf], aAddr + (uint32_t)mf * (16u * AROW));
        ldmx4(&bF[0], bAddr);
        ldmx4(&bF[4], bAddr + 16u * AROW);
#pragma unroll
        for (int mf = 0; mf < 4; mf++)
#pragma unroll
            for (int nf = 0; nf < 4; nf++)
                mma16816(acc[mf][nf], aF[mf], &bF[nf * 2]);
    }

#pragma unroll
    for (int mf = 0; mf < 4; mf++) {
#pragma unroll
        for (int hh = 0; hh < 2; hh++) {
            const int rl = wi * 64 + mf * 16 + hh * 8 + (lane >> 2);
            float* dst = &g_h[(i0 + rl) * 128];
            float p1 = 0.f, p2 = 0.f;
#pragma unroll
            for (int nf = 0; nf < 4; nf++) {
                const int o = obase + nf * 8 + (lane & 3) * 2;
                float v0 = acc[mf][nf][hh * 2 + 0];
                float v1 = acc[mf][nf][hh * 2 + 1];
                float2 r; r.x = v0; r.y = v1;
                *(float2*)&dst[o] = r;
                p1 += v0 * aS[o] + v1 * aS[o + 1];
                p2 += v0 * aS[128 + o] + v1 * aS[128 + o + 1];
            }
            p1 += __shfl_xor_sync(0xffffffffu, p1, 1);
            p1 += __shfl_xor_sync(0xffffffffu, p1, 2);
            p2 += __shfl_xor_sync(0xffffffffu, p2, 1);
            p2 += __shfl_xor_sync(0xffffffffu, p2, 2);
            if ((lane & 3) == 0) { sPS[wo][rl] = p1; sPD[wo][rl] = p2; }
        }
    }
    __syncthreads();
    if (tid < 128) {
        float s1 = sPS[0][tid] + sPS[1][tid] + sPS[2][tid] + sPS[3][tid];
        float s2 = sPD[0][tid] + sPD[1][tid] + sPD[2][tid] + sPD[3][tid];
        g_ssrc[i0 + tid] = s1;
        g_sdst[i0 + tid] = s2;
    }
}

// ---------------------------------------------------------------------------
// K1b: transpose h -> [b][o][j], convert to fp16  (R13 proven version)
// ---------------------------------------------------------------------------
__global__ __launch_bounds__(256) void k1b_split() {
    __shared__ float t[32][33];
    const int b = blockIdx.z;
    const int j0 = blockIdx.x * 32, o0 = blockIdx.y * 32;
    const int tx = threadIdx.x, ty = threadIdx.y;
#pragma unroll
    for (int r = 0; r < 32; r += 8)
        t[ty + r][tx] = g_h[((size_t)b * 2048 + j0 + ty + r) * 128 + o0 + tx];
    __syncthreads();
#pragma unroll
    for (int r = 0; r < 32; r += 8) {
        float v = t[tx][ty + r];
        size_t idx = ((size_t)b * 128 + o0 + ty + r) * 2048 + j0 + tx;
        g_hT[idx] = __float2half_rn(v);
    }
}

// ---------------------------------------------------------------------------
// K3: rank sort — 512 thr (R13 proven version)
// ---------------------------------------------------------------------------
__global__ __launch_bounds__(512) void k3_sort() {
    __shared__ float s[2048];
    __shared__ int part[16][128];
    const int b = blockIdx.y;
    const int tid = threadIdx.x;
    for (int idx = tid; idx < 2048; idx += 512) s[idx] = g_sdst[b * 2048 + idx];
    __syncthreads();
    const int g = tid & 31;
    const int ck = tid >> 5;
    const int jl0 = g * 4;
    const int jg0 = blockIdx.x * 128 + jl0;
    const float4 my = *(const float4*)&s[jg0];
    int r0 = 0, r1 = 0, r2 = 0, r3 = 0;
    const int q0 = ck * 128;
#pragma unroll 8
    for (int q = q0; q < q0 + 128; q += 4) {
        const float4 v = *(const float4*)&s[q];
        r0 += (v.x < my.x) || (v.x == my.x && (q + 0) < (jg0 + 0));
        r1 += (v.x < my.y) || (v.x == my.y && (q + 0) < (jg0 + 1));
        r2 += (v.x < my.z) || (v.x == my.z && (q + 0) < (jg0 + 2));
        r3 += (v.x < my.w) || (v.x == my.w && (q + 0) < (jg0 + 3));
        r0 += (v.y < my.x) || (v.y == my.x && (q + 1) < (jg0 + 0));
        r1 += (v.y < my.y) || (v.y == my.y && (q + 1) < (jg0 + 1));
        r2 += (v.y < my.z) || (v.y == my.z && (q + 1) < (jg0 + 2));
        r3 += (v.y < my.w) || (v.y == my.w && (q + 1) < (jg0 + 3));
        r0 += (v.z < my.x) || (v.z == my.x && (q + 2) < (jg0 + 0));
        r1 += (v.z < my.y) || (v.z == my.y && (q + 2) < (jg0 + 1));
        r2 += (v.z < my.z) || (v.z == my.z && (q + 2) < (jg0 + 2));
        r3 += (v.z < my.w) || (v.z == my.w && (q + 2) < (jg0 + 3));
        r0 += (v.w < my.x) || (v.w == my.x && (q + 3) < (jg0 + 0));
        r1 += (v.w < my.y) || (v.w == my.y && (q + 3) < (jg0 + 1));
        r2 += (v.w < my.z) || (v.w == my.z && (q + 3) < (jg0 + 2));
        r3 += (v.w < my.w) || (v.w == my.w && (q + 3) < (jg0 + 3));
    }
    part[ck][jl0 + 0] = r0; part[ck][jl0 + 1] = r1;
    part[ck][jl0 + 2] = r2; part[ck][jl0 + 3] = r3;
    __syncthreads();
    if (tid < 128) {
        int r = 0;
#pragma unroll
        for (int c = 0; c < 16; c++) r += part[c][tid];
        const float mv = s[blockIdx.x * 128 + tid];
        const int base = b * 2048;
        g_v[base + r]    = mv;
        g_perm[base + r] = blockIdx.x * 128 + tid;
        g_w1[base + r]   = expf(mv);
        g_w02[base + r]  = expf(SLOPE * mv);
    }
}

// ---------------------------------------------------------------------------
// K4a: chunk sums — grid (4, 8, 32), 256 thr
// ---------------------------------------------------------------------------
__global__ __launch_bounds__(256) void k4a_sums() {
    __shared__ float s1[8][33], s02[8][33];
    const int ol = threadIdx.x & 31, rs = threadIdx.x >> 5;
    const int o = blockIdx.x * 32 + ol;
    const int b = blockIdx.y, c = blockIdx.z;
    const int base = b * 2048;
    const int r0 = c * 64 + rs * 8;
    float a1 = 0.f, a02 = 0.f;
#pragma unroll
    for (int r = r0; r < r0 + 8; r++) {
        int j = g_perm[base + r];
        float hv = g_h[((size_t)(base + j)) * 128 + o];
        a1  += g_w1[base + r]  * hv;
        a02 += g_w02[base + r] * hv;
    }
    s1[rs][ol] = a1; s02[rs][ol] = a02;
    __syncthreads();
    if (rs == 0) {
        float t1 = 0.f, t02 = 0.f;
#pragma unroll
        for (int q = 0; q < 8; q++) { t1 += s1[q][ol]; t02 += s02[q][ol]; }
        g_cs1[(b * 32 + c) * 128 + o]  = t1;
        g_cs02[(b * 32 + c) * 128 + o] = t02;
    }
}

// ---------------------------------------------------------------------------
// K4b: scan + table write — grid (4, 8, 32), 256 thr
// ---------------------------------------------------------------------------
__global__ __launch_bounds__(256) void k4b_scan() {
    __shared__ float s1[8][33], s02[8][33];
    const int ol = threadIdx.x & 31, rs = threadIdx.x >> 5;
    const int o = blockIdx.x * 32 + ol;
    const int b = blockIdx.y, c = blockIdx.z;
    const int base = b * 2048;

    float off1 = 0.f, off02 = 0.f, tot1 = 0.f;
#pragma unroll
    for (int q = 0; q < 32; q++) {
        float v1  = g_cs1[(b * 32 + q) * 128 + o];
        float v02 = g_cs02[(b * 32 + q) * 128 + o];
        tot1 += v1;
        if (q < c) { off1 += v1; off02 += v02; }
    }
    const int r0 = c * 64 + rs * 8;
    float a1 = 0.f, a02 = 0.f;
#pragma unroll
    for (int r = r0; r < r0 + 8; r++) {
        int j = g_perm[base + r];
        float hv = g_h[((size_t)(base + j)) * 128 + o];
        a1  += g_w1[base + r]  * hv;
        a02 += g_w02[base + r] * hv;
    }
    s1[rs][ol] = a1; s02[rs][ol] = a02;
    __syncthreads();
    float run1 = off1, run02 = off02;
    for (int q = 0; q < rs; q++) { run1 += s1[q][ol]; run02 += s02[q][ol]; }
    const size_t tbase = ((size_t)b * 2049) * 128 + o;
#pragma unroll
    for (int r = r0; r < r0 + 8; r++) {
        int j = g_perm[base + r];
        float hv = g_h[((size_t)(base + j)) * 128 + o];
        g_suf1[tbase + (size_t)r * 128]  = tot1 - run1;
        run1 += g_w1[base + r] * hv;
        g_pre02[tbase + (size_t)r * 128] = run02;
        run02 += g_w02[base + r] * hv;
    }
    if (c == 31 && rs == 7) {
        g_suf1[tbase + (size_t)2048 * 128]  = 0.f;
        g_pre02[tbase + (size_t)2048 * 128] = run02;
    }
}

// ---------------------------------------------------------------------------
// K4d: denominators — PARALLEL fp32 (grid 8, 256 thr, 8 rows/thread)
// ---------------------------------------------------------------------------
__global__ __launch_bounds__(256) void k4d_scanD() {
    __shared__ float c1[256], c02[256];
    __shared__ float o1[257], o02[257];
    const int b = blockIdx.x;
    const int tid = threadIdx.x;
    const int base = b * 2048;
    const int r0 = tid * 8;
    float s1 = 0.f, s2 = 0.f;
#pragma unroll
    for (int r = r0; r < r0 + 8; r++) { s1 += g_w1[base + r]; s2 += g_w02[base + r]; }
    c1[tid] = s1; c02[tid] = s2;
    __syncthreads();
    if (tid < 32) {
        // lane handles chunks [lane*8, lane*8+8)
        float t1 = 0.f, t2 = 0.f;
#pragma unroll
        for (int q = 0; q < 8; q++) { t1 += c1[tid * 8 + q]; t2 += c02[tid * 8 + q]; }
        // exclusive warp prefix
        float e1 = t1, e2 = t2;
#pragma unroll
        for (int off = 1; off < 32; off <<= 1) {
            float u1 = __shfl_up_sync(0xffffffffu, e1, off);
            float u2 = __shfl_up_sync(0xffffffffu, e2, off);
            if ((tid & 31) >= off) { e1 += u1; e2 += u2; }
        }
        e1 -= t1; e2 -= t2;   // exclusive
        float run1 = e1, run2 = e2;
#pragma unroll
        for (int q = 0; q < 8; q++) {
            o1[tid * 8 + q] = run1;  run1 += c1[tid * 8 + q];
            o02[tid * 8 + q] = run2; run2 += c02[tid * 8 + q];
        }
        if (tid == 31) { o1[256] = run1; o02[256] = run2; }
    }
    __syncthreads();
    const float tot1 = o1[256];
    float run1 = o1[tid], run02 = o02[tid];
    const size_t tb = (size_t)b * 2049;
#pragma unroll
    for (int r = r0; r < r0 + 8; r++) {
        g_sufD1[tb + r] = tot1 - run1;
        run1 += g_w1[base + r];
        g_preD02[tb + r] = run02;
        run02 += g_w02[base + r];
    }
    if (tid == 255) { g_sufD1[tb + 2048] = 0.f; g_preD02[tb + 2048] = run02; }
}

// ---------------------------------------------------------------------------
// K5: fp16 mma.sync GEMM (adj@h) + attention epilogue + lrelu (R13 exact)
// 512 thr, 16 warps = 4(i) x 4(o), warp 32x32. CTA 128x128, K-chunk 128.
// ---------------------------------------------------------------------------
#define TILE_BYTES (128u * AROW)
#define OFF_A 0u
#define OFF_B TILE_BYTES
#define STG_BYTES (2u * TILE_BYTES)
#define K5_SMEM (2u * STG_BYTES)

__global__ __launch_bounds__(512) void k5_main(const float* __restrict__ adj,
                                               float* __restrict__ out) {
    extern __shared__ __align__(128) char dsm[];
    __shared__ int kS[128];
    __shared__ float e1S[128], e02S[128], dinvS[128];
    const uint32_t sb = smem_u32(dsm);
    const int tid = threadIdx.x;
    const int b = blockIdx.y;
    const int i0 = blockIdx.x * 128;

    {
        float* vS = (float*)dsm;
        for (int idx = tid; idx < 2048; idx += 512) vS[idx] = g_v[b * 2048 + idx];
        __syncthreads();
        if (tid < 128) {
            float si = g_ssrc[b * 2048 + i0 + tid];
            float target = -si;
            int lo = 0, hi = 2048;
            while (lo < hi) { int mid = (lo + hi) >> 1; if (vS[mid] < target) lo = mid + 1; else hi = mid; }
            float e1 = expf(si), e02 = expf(SLOPE * si);
            float Dv = e1 * g_sufD1[(size_t)b * 2049 + lo] + e02 * g_preD02[(size_t)b * 2049 + lo];
            kS[tid] = lo; e1S[tid] = e1; e02S[tid] = e02; dinvS[tid] = 1.0f / Dv;
        }
        __syncthreads();
    }

    const int warp = tid >> 5, lane = tid & 31;

    const float* adjT = adj + ((size_t)(b * 2048 + i0)) * 2048;
    const int aRowOff = warp * 2 + (lane >> 4);
    const int aCol = (lane & 15) * 8;
    const uint32_t aSts = (uint32_t)aRowOff * AROW + (uint32_t)aCol * 2;
    const __half* hTb = g_hT + ((size_t)b * 128) * 2048;
    const int bRow = tid >> 4, bSeg = tid & 15;
    const uint32_t bSts = (uint32_t)bRow * AROW + (uint32_t)bSeg * 16;

    const int wi = warp & 3, wo = warp >> 2;
    const int obase = wo * 32;
    const uint32_t aLane = (uint32_t)(wi * 32 + (lane & 15)) * AROW + ((lane >> 4) << 4);
    const uint32_t bLane = (uint32_t)(obase + (lane & 7) + ((lane & 16) >> 1)) * AROW + ((lane & 8) << 1);

    float acc[2][4][4];
#pragma unroll
    for (int mf = 0; mf < 2; mf++)
#pragma unroll
        for (int nf = 0; nf < 4; nf++)
#pragma unroll
            for (int e = 0; e < 4; e++) acc[mf][nf][e] = 0.f;

    {
#pragma unroll
        for (int p = 0; p < 4; p++) {
            const float* src = adjT + (size_t)(p * 32 + aRowOff) * 2048 + aCol;
            float4 u = *(const float4*)src;
            float4 w = *(const float4*)(src + 4);
            sts128(sb + OFF_A + aSts + (uint32_t)p * (32u * AROW),
                   cvt2h(u.y, u.x), cvt2h(u.w, u.z), cvt2h(w.y, w.x), cvt2h(w.w, w.z));
        }
#pragma unroll
        for (int p = 0; p < 4; p++) {
            uint4 v = *(const uint4*)(hTb + (size_t)(p * 32 + bRow) * 2048 + bSeg * 8);
            sts128(sb + OFF_B + bSts + (uint32_t)p * (32u * AROW), v.x, v.y, v.z, v.w);
        }
        __syncthreads();
    }

    for (int c = 0; c < 16; c++) {
        const uint32_t sCur = sb + (c & 1 ? STG_BYTES : 0u);
        const uint32_t sNxt = sb + (c & 1 ? 0u : STG_BYTES);
        const int j1 = (c + 1) * 128;
        float4 fA[8];
        uint4 fB[4];
        if (c < 15) {
#pragma unroll
            for (int p = 0; p < 4; p++) {
                const float* src = adjT + (size_t)(p * 32 + aRowOff) * 2048 + j1 + aCol;
                fA[p * 2]     = *(const float4*)src;
                fA[p * 2 + 1] = *(const float4*)(src + 4);
            }
#pragma unroll
            for (int p = 0; p < 4; p++)
                fB[p] = *(const uint4*)(hTb + (size_t)(p * 32 + bRow) * 2048 + j1 + bSeg * 8);
        }
#pragma unroll
        for (int kk = 0; kk < 8; kk++) {
            uint32_t aF[2][4], bF[8];
            const uint32_t aAddr = sCur + OFF_A + aLane + kk * 32;
            const uint32_t bAddr = sCur + OFF_B + bLane + kk * 32;
            ldmx4(aF[0], aAddr);
            ldmx4(aF[1], aAddr + 16u * AROW);
            ldmx4(&bF[0], bAddr);
            ldmx4(&bF[4], bAddr + 16u * AROW);
#pragma unroll
            for (int mf = 0; mf < 2; mf++)
#pragma unroll
                for (int nf = 0; nf < 4; nf++)
                    mma16816(acc[mf][nf], aF[mf], &bF[nf * 2]);
        }
        if (c < 15) {
#pragma unroll
            for (int p = 0; p < 4; p++) {
                float4 u = fA[p * 2], w = fA[p * 2 + 1];
                sts128(sNxt + OFF_A + aSts + (uint32_t)p * (32u * AROW),
                       cvt2h(u.y, u.x), cvt2h(u.w, u.z), cvt2h(w.y, w.x), cvt2h(w.w, w.z));
            }
#pragma unroll
            for (int p = 0; p < 4; p++)
                sts128(sNxt + OFF_B + bSts + (uint32_t)p * (32u * AROW),
                       fB[p].x, fB[p].y, fB[p].z, fB[p].w);
        }
        __syncthreads();
    }

#pragma unroll
    for (int mf = 0; mf < 2; mf++) {
        const int rl0 = wi * 32 + mf * 16 + (lane >> 2);
#pragma unroll
        for (int hh = 0; hh < 2; hh++) {
            const int rl = rl0 + hh * 8;
            const int k = kS[rl];
            const float e1 = e1S[rl], e02 = e02S[rl], dinv = dinvS[rl];
            const float* suf = &g_suf1[((size_t)(b * 2049 + k)) * 128];
            const float* pre = &g_pre02[((size_t)(b * 2049 + k)) * 128];
            float* dst = &out[((size_t)(b * 2048 + i0 + rl)) * 128];
#pragma unroll
            for (int nf = 0; nf < 4; nf++) {
                const int o = obase + nf * 8 + (lane & 3) * 2;
                float2 sf = *(const float2*)&suf[o];
                float2 pf = *(const float2*)&pre[o];
                float v0 = acc[mf][nf][hh * 2 + 0] + (e1 * sf.x + e02 * pf.x) * dinv;
                float v1 = acc[mf][nf][hh * 2 + 1] + (e1 * sf.y + e02 * pf.y) * dinv;
                float2 r;
                r.x = v0 >= 0.f ? v0 : SLOPE * v0;
                r.y = v1 >= 0.f ? v1 : SLOPE * v1;
                *(float2*)&dst[o] = r;
            }
        }
    }
}

// ---------------------------------------------------------------------------
extern "C" void kernel_launch(void* const* d_in, const int* in_sizes, int n_in,
                              void* d_out, int out_size) {
    (void)in_sizes; (void)n_in; (void)out_size;
    const float* x   = (const float*)d_in[0];
    const float* adj = (const float*)d_in[1];
    const float* W   = (const float*)d_in[2];
    const float* a   = (const float*)d_in[3];
    float* out = (float*)d_out;

    cudaFuncSetAttribute(k1_mma, cudaFuncAttributeMaxDynamicSharedMemorySize, K1_SMEM);
    cudaFuncSetAttribute(k5_main, cudaFuncAttributeMaxDynamicSharedMemorySize, K5_SMEM);

    k0_wt<<<dim3(4, 4), dim3(32, 8)>>>(W);
    k1_mma<<<128, 256, K1_SMEM>>>(x, a);
    k1b_split<<<dim3(64, 4, 8), dim3(32, 8)>>>();
    k3_sort<<<dim3(16, 8), 512>>>();
    k4a_sums<<<dim3(4, 8, 32), 256>>>();
    k4b_scan<<<dim3(4, 8, 32), 256>>>();
    k4d_scanD<<<8, 256>>>();
    k5_main<<<dim3(16, 8), 512, K5_SMEM>>>(adj, out);
}